// round 12
// baseline (speedup 1.0000x reference)
#include <cuda_runtime.h>
#include <cstdint>

typedef unsigned u32;

#define NPX (512 * 1024)
#define LRN (256 * 512)
#define NTILES 4096            // 4096 tiles x 128 px
#define PSTR 132               // act pair-buffer row stride (uint2 units); 132 % 16 == 4 -> conflict-free LDS.64

// ---------------- interleaved (hi,lo) packed-bf16 weights in global scratch ----------------
// entry (m, kp): [0]=pack(bf16 hi of w[m][2kp], w[m][2kp+1]), [1]=residual pack
__device__ __align__(16) u32 g_w0p[128 * 68 * 2];
__device__ __align__(16) u32 g_w1p[64 * 68 * 2];
__device__ __align__(16) u32 g_w2p[32 * 36 * 2];
__device__ __align__(16) u32 g_w3p[16 * 20 * 2];

// pack two fp32 -> bf16x2 (first arg -> low half, second -> high half)
__device__ __forceinline__ u32 pkbf(float lo, float hi) {
    u32 r; asm("cvt.rn.bf16x2.f32 %0, %1, %2;" : "=r"(r) : "f"(hi), "f"(lo)); return r;
}
__device__ __forceinline__ float bflo(u32 p) { return __uint_as_float(p << 16); }
__device__ __forceinline__ float bfhi(u32 p) { return __uint_as_float(p & 0xFFFF0000u); }
__device__ __forceinline__ float lrelu(float x) { return fmaxf(x, 0.01f * x); }

// ---------------- prep: fp32 weights -> interleaved packed bf16 hi/lo ----------------
__global__ void cmfsm_prep(const float* __restrict__ w0, const float* __restrict__ w1,
                           const float* __restrict__ w2, const float* __restrict__ w3) {
    int t = blockIdx.x * blockDim.x + threadIdx.x;
    int n = gridDim.x * blockDim.x;
    for (int i = t; i < 128 * 64; i += n) {
        int m = i >> 6, kp = i & 63;
        float v0 = w0[m * 128 + 2 * kp], v1 = w0[m * 128 + 2 * kp + 1];
        u32 h = pkbf(v0, v1);
        g_w0p[(m * 68 + kp) * 2]     = h;
        g_w0p[(m * 68 + kp) * 2 + 1] = pkbf(v0 - bflo(h), v1 - bfhi(h));
    }
    for (int i = t; i < 64 * 64; i += n) {
        int m = i >> 6, kp = i & 63;
        float v0 = w1[m * 128 + 2 * kp], v1 = w1[m * 128 + 2 * kp + 1];
        u32 h = pkbf(v0, v1);
        g_w1p[(m * 68 + kp) * 2]     = h;
        g_w1p[(m * 68 + kp) * 2 + 1] = pkbf(v0 - bflo(h), v1 - bfhi(h));
    }
    for (int i = t; i < 32 * 32; i += n) {
        int m = i >> 5, kp = i & 31;
        float v0 = w2[m * 64 + 2 * kp], v1 = w2[m * 64 + 2 * kp + 1];
        u32 h = pkbf(v0, v1);
        g_w2p[(m * 36 + kp) * 2]     = h;
        g_w2p[(m * 36 + kp) * 2 + 1] = pkbf(v0 - bflo(h), v1 - bfhi(h));
    }
    for (int i = t; i < 16 * 16; i += n) {
        int m = i >> 4, kp = i & 15;
        float v0 = w3[m * 32 + 2 * kp], v1 = w3[m * 32 + 2 * kp + 1];
        u32 h = pkbf(v0, v1);
        g_w3p[(m * 20 + kp) * 2]     = h;
        g_w3p[(m * 20 + kp) * 2 + 1] = pkbf(v0 - bflo(h), v1 - bfhi(h));
    }
}

// ---------------- smem layout (bytes) ----------------
#define OBUF  0                         // act pair buffer: 64 pairrows x 132 x 8B = 67584
#define OW0   67584                     // 128x68x8 = 69632
#define OW1   137216                    // 64x68x8 = 34816
#define OW2   172032                    // 32x36x8 = 9216
#define OW3   181248                    // 16x20x8 = 2560
#define OSACT 183808                    // 128 px x 17 f32 = 8704
#define SMEMSZ 192512

// ---------------- mma.m16n8k16 bf16 ----------------
__device__ __forceinline__ void mma16(float* c, const u32* a, u32 b0, u32 b1) {
    asm volatile(
        "mma.sync.aligned.m16n8k16.row.col.f32.bf16.bf16.f32 "
        "{%0,%1,%2,%3}, {%4,%5,%6,%7}, {%8,%9}, {%0,%1,%2,%3};"
        : "+f"(c[0]), "+f"(c[1]), "+f"(c[2]), "+f"(c[3])
        : "r"(a[0]), "r"(a[1]), "r"(a[2]), "r"(a[3]), "r"(b0), "r"(b1));
}

// write one (hi,lo) act pair: k-values (2*pr, 2*pr+1) at pixel px
__device__ __forceinline__ void wpair(uint2* bufp, int pr, int px, float v0, float v1) {
    u32 h = pkbf(v0, v1);
    u32 l = pkbf(v0 - bflo(h), v1 - bfhi(h));
    bufp[pr * PSTR + px] = make_uint2(h, l);
}

// GEMM: C[MT][NT][4] += (Wh+Wl) @ (bh+bl), 3-term bf16, pre-packed operands. K = 16*KT.
template <int MT, int NT, int KT, int WS>
__device__ __forceinline__ void gemm_p(const uint2* W, const uint2* B, float* C,
                                       int m0, int px0, int lane) {
    const int r = lane >> 2, c = lane & 3;
#pragma unroll 2
    for (int kt = 0; kt < KT; kt++) {
        const int kp0 = kt * 8;
        u32 ah[MT][4], al[MT][4];
#pragma unroll
        for (int mt = 0; mt < MT; mt++) {
            const uint2* p = W + (m0 + 16 * mt + r) * WS + kp0 + c;
            uint2 q0 = p[0], q2 = p[4], q1 = p[8 * WS], q3 = p[8 * WS + 4];
            ah[mt][0] = q0.x; al[mt][0] = q0.y;
            ah[mt][1] = q1.x; al[mt][1] = q1.y;
            ah[mt][2] = q2.x; al[mt][2] = q2.y;
            ah[mt][3] = q3.x; al[mt][3] = q3.y;
        }
#pragma unroll
        for (int nt = 0; nt < NT; nt++) {
            const int pxn = px0 + 8 * nt + r;
            uint2 b0 = B[(kp0 + c) * PSTR + pxn];
            uint2 b1 = B[(kp0 + c + 4) * PSTR + pxn];
#pragma unroll
            for (int mt = 0; mt < MT; mt++) {
                float* cc = C + (mt * NT + nt) * 4;
                mma16(cc, ah[mt], b0.x, b1.x);
                mma16(cc, ah[mt], b0.y, b1.y);
                mma16(cc, al[mt], b0.x, b1.x);
            }
        }
    }
}

// epilogue: lrelu(C) -> packed (hi,lo) pairs in bufp. Pairs k-adjacent rows via shfl.
template <int MT, int NT>
__device__ __forceinline__ void epi_pack(uint2* bufp, const float* C, int m0, int px0,
                                         int lane) {
    const int r = lane >> 2, c = lane & 3;
    const int odd = r & 1;
#pragma unroll
    for (int mt = 0; mt < MT; mt++)
#pragma unroll
        for (int nt = 0; nt < NT; nt++) {
            const float* cc = C + (mt * NT + nt) * 4;
            float v0 = lrelu(cc[0]);   // row m0+16mt+r,   px P
            float v1 = lrelu(cc[1]);   // row m0+16mt+r,   px P+1
            float v2 = lrelu(cc[2]);   // row m0+16mt+r+8, px P
            float v3 = lrelu(cc[3]);   // row m0+16mt+r+8, px P+1
            float u0 = __shfl_xor_sync(0xffffffffu, v0, 4);
            float u1 = __shfl_xor_sync(0xffffffffu, v1, 4);
            float u2 = __shfl_xor_sync(0xffffffffu, v2, 4);
            float u3 = __shfl_xor_sync(0xffffffffu, v3, 4);
            float e0 = odd ? u1 : v0;  // even-row value at pxw
            float o0 = odd ? v1 : u0;  // odd-row value at pxw
            float e1 = odd ? u3 : v2;
            float o1 = odd ? v3 : u2;
            int pxw = px0 + 8 * nt + 2 * c + odd;
            int pr0 = (m0 + 16 * mt + (r & 6)) >> 1;
            wpair(bufp, pr0, pxw, e0, o0);
            wpair(bufp, pr0 + 4, pxw, e1, o1);
        }
}

__global__ void __launch_bounds__(256, 1)
cmfsm_main(const float* __restrict__ lr, const float* __restrict__ hr,
           const float* __restrict__ w4, const float* __restrict__ w5,
           const float* __restrict__ s2w0, const float* __restrict__ s2w1,
           const float* __restrict__ s2w2, const float* __restrict__ fw,
           float* __restrict__ out) {
    extern __shared__ __align__(16) char sm8[];
    uint2* bufp = (uint2*)(sm8 + OBUF);
    uint2* W0p  = (uint2*)(sm8 + OW0);
    uint2* W1p  = (uint2*)(sm8 + OW1);
    uint2* W2p  = (uint2*)(sm8 + OW2);
    uint2* W3p  = (uint2*)(sm8 + OW3);
    float* sact = (float*)(sm8 + OSACT);

    const int tid  = threadIdx.x;
    const int wid  = tid >> 5;
    const int lane = tid & 31;

    // weights: L2 scratch -> smem, once per (persistent) block
    {
        const uint4* s; uint4* d;
        s = (const uint4*)g_w0p; d = (uint4*)W0p;
        for (int i = tid; i < 4352; i += 256) d[i] = s[i];
        s = (const uint4*)g_w1p; d = (uint4*)W1p;
        for (int i = tid; i < 2176; i += 256) d[i] = s[i];
        s = (const uint4*)g_w2p; d = (uint4*)W2p;
        for (int i = tid; i < 576; i += 256) d[i] = s[i];
        s = (const uint4*)g_w3p; d = (uint4*)W3p;
        for (int i = tid; i < 160; i += 256) d[i] = s[i];
    }
    __syncthreads();

    for (int tile = blockIdx.x; tile < NTILES; tile += gridDim.x) {
        const int pxb = tile << 7;
        const int hb  = pxb >> 10;
        const int wbp = pxb & 1023;

        // ---- rep build (packed pairs): pairrows 0-15 a, 16-31 b, 32-47 a*b, 48-63 (a-b)^2 ----
        {
            const int g  = tid >> 7;          // 0..1 -> 16 channels each
            const int px = tid & 127;
            const int li = ((hb >> 1) << 9) + ((wbp + px) >> 1);
            const float* hp = hr + (size_t)(16 * g) * NPX + (pxb + px);
            const float* lp = lr + (size_t)(16 * g) * LRN + li;
            float a[16], b[16];
#pragma unroll
            for (int i = 0; i < 16; i++) { a[i] = lp[(size_t)i * LRN]; b[i] = hp[(size_t)i * NPX]; }
#pragma unroll
            for (int j = 0; j < 8; j++) {
                float a0 = a[2 * j], a1 = a[2 * j + 1];
                float b0 = b[2 * j], b1 = b[2 * j + 1];
                float d0 = a0 - b0, d1 = a1 - b1;
                int pr = 8 * g + j;
                wpair(bufp, pr,      px, a0, a1);
                wpair(bufp, 16 + pr, px, b0, b1);
                wpair(bufp, 32 + pr, px, a0 * b0, a1 * b1);
                wpair(bufp, 48 + pr, px, d0 * d0, d1 * d1);
            }
        }
        __syncthreads();

        // ---- GEMM1: 128 <- rep(128); warp grid 4(m) x 2(px) ----
        {
            float C1[2 * 8 * 4];
#pragma unroll
            for (int i = 0; i < 64; i++) C1[i] = 0.f;
            int m0 = 32 * (wid & 3), px0 = 64 * (wid >> 2);
            gemm_p<2, 8, 8, 68>(W0p, bufp, C1, m0, px0, lane);
            __syncthreads();
            epi_pack<2, 8>(bufp, C1, m0, px0, lane);
        }
        __syncthreads();

        // ---- GEMM2: 64 <- act1(128); warp grid 2(m) x 4(px) ----
        {
            float C2[2 * 4 * 4];
#pragma unroll
            for (int i = 0; i < 32; i++) C2[i] = 0.f;
            int m0 = 32 * (wid & 1), px0 = 32 * (wid >> 1);
            gemm_p<2, 4, 8, 68>(W1p, bufp, C2, m0, px0, lane);
            __syncthreads();
            epi_pack<2, 4>(bufp, C2, m0, px0, lane);
        }
        __syncthreads();

        // ---- GEMM3: 32 <- act2(64); warp grid 2(m) x 4(px) ----
        {
            float C3[1 * 4 * 4];
#pragma unroll
            for (int i = 0; i < 16; i++) C3[i] = 0.f;
            int m0 = 16 * (wid & 1), px0 = 32 * (wid >> 1);
            gemm_p<1, 4, 4, 36>(W2p, bufp, C3, m0, px0, lane);
            __syncthreads();
            epi_pack<1, 4>(bufp, C3, m0, px0, lane);
        }
        __syncthreads();

        // ---- GEMM4: 16 <- act3(32); 8 warps x 16 px (NT=2) -> SACT [px][16] fp32 ----
        {
            float C4[2 * 4];
#pragma unroll
            for (int i = 0; i < 8; i++) C4[i] = 0.f;
            int px0 = 16 * wid;
            gemm_p<1, 2, 2, 20>(W3p, bufp, C4, 0, px0, lane);
            const int r = lane >> 2, c = lane & 3;
#pragma unroll
            for (int nt = 0; nt < 2; nt++) {
                const float* cc = C4 + nt * 4;
                int px = px0 + 8 * nt + 2 * c;
                sact[px * 17 + r]           = lrelu(cc[0]);
                sact[(px + 1) * 17 + r]     = lrelu(cc[1]);
                sact[px * 17 + r + 8]       = lrelu(cc[2]);
                sact[(px + 1) * 17 + r + 8] = lrelu(cc[3]);
            }
        }
        __syncthreads();

        // ---- scalar finish: layers 5,6 + weights2 + fuse (exact fp32) ----
        if (tid < 128) {
            const float* o4 = sact + tid * 17;
            float w1v = 0.f;
#pragma unroll
            for (int cc = 0; cc < 8; cc++) {
                float n5 = 0.f;
#pragma unroll
                for (int k = 0; k < 16; k++) n5 = fmaf(w4[cc * 16 + k], o4[k], n5);
                w1v = fmaf(w5[cc], n5, w1v);
            }
            float dx = ((wbp + tid) & 1) ? 1.0f : -1.0f;
            float dy = (hb & 1) ? 1.0f : -1.0f;
            const float nm = 1.41421356237309515f;
            float t0 = lrelu(s2w0[0] * dx + s2w0[1] * dy + s2w0[2] * nm);
            float t1 = lrelu(s2w0[3] * dx + s2w0[4] * dy + s2w0[5] * nm);
            float t2 = lrelu(s2w0[6] * dx + s2w0[7] * dy + s2w0[8] * nm);
            float u0 = lrelu(s2w1[0] * t0 + s2w1[1] * t1 + s2w1[2] * t2);
            float u1 = lrelu(s2w1[3] * t0 + s2w1[4] * t1 + s2w1[5] * t2);
            float w2v = s2w2[0] * u0 + s2w2[1] * u1;
            out[pxb + tid] = fabsf(fw[0]) * w1v + fabsf(fw[1]) * w2v;
        }
        __syncthreads();
    }
}

extern "C" void kernel_launch(void* const* d_in, const int* in_sizes, int n_in,
                              void* d_out, int out_size) {
    const float* lr   = (const float*)d_in[0];
    const float* hr   = (const float*)d_in[1];
    const float* w0   = (const float*)d_in[2];
    const float* w1   = (const float*)d_in[3];
    const float* w2   = (const float*)d_in[4];
    const float* w3   = (const float*)d_in[5];
    const float* w4   = (const float*)d_in[6];
    const float* w5   = (const float*)d_in[7];
    const float* s2w0 = (const float*)d_in[8];
    const float* s2w1 = (const float*)d_in[9];
    const float* s2w2 = (const float*)d_in[10];
    const float* fw   = (const float*)d_in[11];

    cmfsm_prep<<<64, 256>>>(w0, w1, w2, w3);

    int sms = 148;
    cudaDeviceGetAttribute(&sms, cudaDevAttrMultiProcessorCount, 0);
    if (sms > NTILES) sms = NTILES;

    cudaFuncSetAttribute(cmfsm_main, cudaFuncAttributeMaxDynamicSharedMemorySize, SMEMSZ);
    cmfsm_main<<<sms, 256, SMEMSZ>>>(lr, hr, w4, w5, s2w0, s2w1, s2w2, fw, (float*)d_out);
}

// round 13
// speedup vs baseline: 1.0384x; 1.0384x over previous
#include <cuda_runtime.h>
#include <cstdint>

typedef unsigned u32;

#define NPX (512 * 1024)
#define LRN (256 * 512)
#define NTILES 4096            // 4096 tiles x 128 px
#define PSTR 132               // act pair-buffer row stride (uint2 units); PSTR%16==4 -> conflict-free LDS.64

// ---------------- interleaved (hi,lo) packed-bf16 weights in global scratch ----------------
// k-pair permutation: pair kp = 8t+r holds channels (16t+r, 16t+r+8)
__device__ __align__(16) u32 g_w0p[128 * 68 * 2];
__device__ __align__(16) u32 g_w1p[64 * 68 * 2];
__device__ __align__(16) u32 g_w2p[32 * 36 * 2];
__device__ __align__(16) u32 g_w3p[16 * 20 * 2];

// pack two fp32 -> bf16x2 (first arg -> low half, second -> high half)
__device__ __forceinline__ u32 pkbf(float lo, float hi) {
    u32 r; asm("cvt.rn.bf16x2.f32 %0, %1, %2;" : "=r"(r) : "f"(hi), "f"(lo)); return r;
}
__device__ __forceinline__ float bflo(u32 p) { return __uint_as_float(p << 16); }
__device__ __forceinline__ float bfhi(u32 p) { return __uint_as_float(p & 0xFFFF0000u); }
__device__ __forceinline__ float lrelu(float x) { return fmaxf(x, 0.01f * x); }

// ---------------- prep: fp32 weights -> interleaved packed bf16 hi/lo, k-pair permuted ----------------
__global__ void cmfsm_prep(const float* __restrict__ w0, const float* __restrict__ w1,
                           const float* __restrict__ w2, const float* __restrict__ w3) {
    int t = blockIdx.x * blockDim.x + threadIdx.x;
    int n = gridDim.x * blockDim.x;
    for (int i = t; i < 128 * 64; i += n) {           // W0 [128][128]
        int m = i >> 6, kp = i & 63;
        int k1 = 16 * (kp >> 3) + (kp & 7), k2 = k1 + 8;
        float v0 = w0[m * 128 + k1], v1 = w0[m * 128 + k2];
        u32 h = pkbf(v0, v1);
        g_w0p[(m * 68 + kp) * 2]     = h;
        g_w0p[(m * 68 + kp) * 2 + 1] = pkbf(v0 - bflo(h), v1 - bfhi(h));
    }
    for (int i = t; i < 64 * 64; i += n) {            // W1 [64][128]
        int m = i >> 6, kp = i & 63;
        int k1 = 16 * (kp >> 3) + (kp & 7), k2 = k1 + 8;
        float v0 = w1[m * 128 + k1], v1 = w1[m * 128 + k2];
        u32 h = pkbf(v0, v1);
        g_w1p[(m * 68 + kp) * 2]     = h;
        g_w1p[(m * 68 + kp) * 2 + 1] = pkbf(v0 - bflo(h), v1 - bfhi(h));
    }
    for (int i = t; i < 32 * 32; i += n) {            // W2 [32][64]
        int m = i >> 5, kp = i & 31;
        int k1 = 16 * (kp >> 3) + (kp & 7), k2 = k1 + 8;
        float v0 = w2[m * 64 + k1], v1 = w2[m * 64 + k2];
        u32 h = pkbf(v0, v1);
        g_w2p[(m * 36 + kp) * 2]     = h;
        g_w2p[(m * 36 + kp) * 2 + 1] = pkbf(v0 - bflo(h), v1 - bfhi(h));
    }
    for (int i = t; i < 16 * 16; i += n) {            // W3 [16][32]
        int m = i >> 4, kp = i & 15;
        int k1 = 16 * (kp >> 3) + (kp & 7), k2 = k1 + 8;
        float v0 = w3[m * 32 + k1], v1 = w3[m * 32 + k2];
        u32 h = pkbf(v0, v1);
        g_w3p[(m * 20 + kp) * 2]     = h;
        g_w3p[(m * 20 + kp) * 2 + 1] = pkbf(v0 - bflo(h), v1 - bfhi(h));
    }
}

// ---------------- smem layout (bytes) ----------------
#define OBUF  0                         // act pair buffer: 64 pairrows x 132 x 8B = 67584
#define OW0   67584                     // 128x68x8 = 69632
#define OW1   137216                    // 64x68x8 = 34816
#define OW2   172032                    // 32x36x8 = 9216
#define OW3   181248                    // 16x20x8 = 2560
#define OSACT 183808                    // 128 px x 17 f32 = 8704
#define SMEMSZ 192512

// ---------------- mma.m16n8k16 bf16 ----------------
__device__ __forceinline__ void mma16(float* c, const u32* a, u32 b0, u32 b1) {
    asm volatile(
        "mma.sync.aligned.m16n8k16.row.col.f32.bf16.bf16.f32 "
        "{%0,%1,%2,%3}, {%4,%5,%6,%7}, {%8,%9}, {%0,%1,%2,%3};"
        : "+f"(c[0]), "+f"(c[1]), "+f"(c[2]), "+f"(c[3])
        : "r"(a[0]), "r"(a[1]), "r"(a[2]), "r"(a[3]), "r"(b0), "r"(b1));
}

// write one (hi,lo) act pair at pair-row pr, pixel px; pair = (v0, v1)
__device__ __forceinline__ void wpair(uint2* bufp, int pr, int px, float v0, float v1) {
    u32 h = pkbf(v0, v1);
    u32 l = pkbf(v0 - bflo(h), v1 - bfhi(h));
    bufp[pr * PSTR + px] = make_uint2(h, l);
}

// GEMM: C[MT][NT][4] += (Wh+Wl) @ (bh+bl), 3-term bf16, pre-packed operands. K = 16*KT (virtual).
template <int MT, int NT, int KT, int WS>
__device__ __forceinline__ void gemm_p(const uint2* W, const uint2* B, float* C,
                                       int m0, int px0, int lane) {
    const int r = lane >> 2, c = lane & 3;
#pragma unroll 2
    for (int kt = 0; kt < KT; kt++) {
        const int kp0 = kt * 8;
        u32 ah[MT][4], al[MT][4];
#pragma unroll
        for (int mt = 0; mt < MT; mt++) {
            const uint2* p = W + (m0 + 16 * mt + r) * WS + kp0 + c;
            uint2 q0 = p[0], q2 = p[4], q1 = p[8 * WS], q3 = p[8 * WS + 4];
            ah[mt][0] = q0.x; al[mt][0] = q0.y;
            ah[mt][1] = q1.x; al[mt][1] = q1.y;
            ah[mt][2] = q2.x; al[mt][2] = q2.y;
            ah[mt][3] = q3.x; al[mt][3] = q3.y;
        }
#pragma unroll
        for (int nt = 0; nt < NT; nt++) {
            const int pxn = px0 + 8 * nt + r;
            uint2 b0 = B[(kp0 + c) * PSTR + pxn];
            uint2 b1 = B[(kp0 + c + 4) * PSTR + pxn];
#pragma unroll
            for (int mt = 0; mt < MT; mt++) {
                float* cc = C + (mt * NT + nt) * 4;
                mma16(cc, ah[mt], b0.x, b1.x);
                mma16(cc, ah[mt], b0.y, b1.y);
                mma16(cc, al[mt], b0.x, b1.x);
            }
        }
    }
}

// epilogue: lrelu(C) -> packed (hi,lo) pairs, shuffle-free.
// Thread owns rows (ch, ch+8) at pixels (P, P+1) -> exactly one pair-row, two pixels.
template <int MT, int NT>
__device__ __forceinline__ void epi_pack(uint2* bufp, const float* C, int m0, int px0,
                                         int lane) {
    const int r = lane >> 2, c = lane & 3;
#pragma unroll
    for (int mt = 0; mt < MT; mt++)
#pragma unroll
        for (int nt = 0; nt < NT; nt++) {
            const float* cc = C + (mt * NT + nt) * 4;
            int pr = 8 * (m0 / 16 + mt) + r;       // pair (ch, ch+8), ch = m0+16mt+r
            int P  = px0 + 8 * nt + 2 * c;
            wpair(bufp, pr, P,     lrelu(cc[0]), lrelu(cc[2]));
            wpair(bufp, pr, P + 1, lrelu(cc[1]), lrelu(cc[3]));
        }
}

__global__ void __launch_bounds__(256, 1)
cmfsm_main(const float* __restrict__ lr, const float* __restrict__ hr,
           const float* __restrict__ w4, const float* __restrict__ w5,
           const float* __restrict__ s2w0, const float* __restrict__ s2w1,
           const float* __restrict__ s2w2, const float* __restrict__ fw,
           float* __restrict__ out) {
    extern __shared__ __align__(16) char sm8[];
    uint2* bufp = (uint2*)(sm8 + OBUF);
    uint2* W0p  = (uint2*)(sm8 + OW0);
    uint2* W1p  = (uint2*)(sm8 + OW1);
    uint2* W2p  = (uint2*)(sm8 + OW2);
    uint2* W3p  = (uint2*)(sm8 + OW3);
    float* sact = (float*)(sm8 + OSACT);

    const int tid  = threadIdx.x;
    const int wid  = tid >> 5;
    const int lane = tid & 31;

    // weights: L2 scratch -> smem, once per (persistent) block
    {
        const uint4* s; uint4* d;
        s = (const uint4*)g_w0p; d = (uint4*)W0p;
        for (int i = tid; i < 4352; i += 256) d[i] = s[i];
        s = (const uint4*)g_w1p; d = (uint4*)W1p;
        for (int i = tid; i < 2176; i += 256) d[i] = s[i];
        s = (const uint4*)g_w2p; d = (uint4*)W2p;
        for (int i = tid; i < 576; i += 256) d[i] = s[i];
        s = (const uint4*)g_w3p; d = (uint4*)W3p;
        for (int i = tid; i < 160; i += 256) d[i] = s[i];
    }
    __syncthreads();

    for (int tile = blockIdx.x; tile < NTILES; tile += gridDim.x) {
        const int pxb = tile << 7;
        const int hb  = pxb >> 10;
        const int wbp = pxb & 1023;

        // ---- rep build: pairs (ch, ch+8) within each 16-ch block ----
        // plane p (a,b,ab,dd) occupies pair-rows 16p..16p+15; group g covers 8 of them.
        {
            const int g  = tid >> 7;          // 0..1 -> 16 channels each
            const int px = tid & 127;
            const int li = ((hb >> 1) << 9) + ((wbp + px) >> 1);
            const float* hp = hr + (size_t)(16 * g) * NPX + (pxb + px);
            const float* lp = lr + (size_t)(16 * g) * LRN + li;
            float a[16], b[16];
#pragma unroll
            for (int i = 0; i < 16; i++) { a[i] = lp[(size_t)i * LRN]; b[i] = hp[(size_t)i * NPX]; }
#pragma unroll
            for (int i = 0; i < 8; i++) {
                float a0 = a[i], a1 = a[i + 8];
                float b0 = b[i], b1 = b[i + 8];
                float d0 = a0 - b0, d1 = a1 - b1;
                int pr = 8 * g + i;
                wpair(bufp, pr,      px, a0, a1);
                wpair(bufp, 16 + pr, px, b0, b1);
                wpair(bufp, 32 + pr, px, a0 * b0, a1 * b1);
                wpair(bufp, 48 + pr, px, d0 * d0, d1 * d1);
            }
        }
        __syncthreads();

        // ---- GEMM1: 128 <- rep(128); warp grid 4(m) x 2(px) ----
        {
            float C1[2 * 8 * 4];
#pragma unroll
            for (int i = 0; i < 64; i++) C1[i] = 0.f;
            int m0 = 32 * (wid & 3), px0 = 64 * (wid >> 2);
            gemm_p<2, 8, 8, 68>(W0p, bufp, C1, m0, px0, lane);
            __syncthreads();
            epi_pack<2, 8>(bufp, C1, m0, px0, lane);
        }
        __syncthreads();

        // ---- GEMM2: 64 <- act1(128); warp grid 2(m) x 4(px) ----
        {
            float C2[2 * 4 * 4];
#pragma unroll
            for (int i = 0; i < 32; i++) C2[i] = 0.f;
            int m0 = 32 * (wid & 1), px0 = 32 * (wid >> 1);
            gemm_p<2, 4, 8, 68>(W1p, bufp, C2, m0, px0, lane);
            __syncthreads();
            epi_pack<2, 4>(bufp, C2, m0, px0, lane);
        }
        __syncthreads();

        // ---- GEMM3: 32 <- act2(64); warp grid 2(m) x 4(px) ----
        {
            float C3[1 * 4 * 4];
#pragma unroll
            for (int i = 0; i < 16; i++) C3[i] = 0.f;
            int m0 = 16 * (wid & 1), px0 = 32 * (wid >> 1);
            gemm_p<1, 4, 4, 36>(W2p, bufp, C3, m0, px0, lane);
            __syncthreads();
            epi_pack<1, 4>(bufp, C3, m0, px0, lane);
        }
        __syncthreads();

        // ---- GEMM4: 16 <- act3(32); 8 warps x 16 px (NT=2) -> SACT [px][16] fp32 ----
        {
            float C4[2 * 4];
#pragma unroll
            for (int i = 0; i < 8; i++) C4[i] = 0.f;
            int px0 = 16 * wid;
            gemm_p<1, 2, 2, 20>(W3p, bufp, C4, 0, px0, lane);
            const int r = lane >> 2, c = lane & 3;
#pragma unroll
            for (int nt = 0; nt < 2; nt++) {
                const float* cc = C4 + nt * 4;
                int px = px0 + 8 * nt + 2 * c;
                sact[px * 17 + r]           = lrelu(cc[0]);
                sact[(px + 1) * 17 + r]     = lrelu(cc[1]);
                sact[px * 17 + r + 8]       = lrelu(cc[2]);
                sact[(px + 1) * 17 + r + 8] = lrelu(cc[3]);
            }
        }
        __syncthreads();

        // ---- scalar finish: layers 5,6 + weights2 + fuse (exact fp32) ----
        if (tid < 128) {
            const float* o4 = sact + tid * 17;
            float w1v = 0.f;
#pragma unroll
            for (int cc = 0; cc < 8; cc++) {
                float n5 = 0.f;
#pragma unroll
                for (int k = 0; k < 16; k++) n5 = fmaf(w4[cc * 16 + k], o4[k], n5);
                w1v = fmaf(w5[cc], n5, w1v);
            }
            float dx = ((wbp + tid) & 1) ? 1.0f : -1.0f;
            float dy = (hb & 1) ? 1.0f : -1.0f;
            const float nm = 1.41421356237309515f;
            float t0 = lrelu(s2w0[0] * dx + s2w0[1] * dy + s2w0[2] * nm);
            float t1 = lrelu(s2w0[3] * dx + s2w0[4] * dy + s2w0[5] * nm);
            float t2 = lrelu(s2w0[6] * dx + s2w0[7] * dy + s2w0[8] * nm);
            float u0 = lrelu(s2w1[0] * t0 + s2w1[1] * t1 + s2w1[2] * t2);
            float u1 = lrelu(s2w1[3] * t0 + s2w1[4] * t1 + s2w1[5] * t2);
            float w2v = s2w2[0] * u0 + s2w2[1] * u1;
            out[pxb + tid] = fabsf(fw[0]) * w1v + fabsf(fw[1]) * w2v;
        }
        __syncthreads();
    }
}

extern "C" void kernel_launch(void* const* d_in, const int* in_sizes, int n_in,
                              void* d_out, int out_size) {
    const float* lr   = (const float*)d_in[0];
    const float* hr   = (const float*)d_in[1];
    const float* w0   = (const float*)d_in[2];
    const float* w1   = (const float*)d_in[3];
    const float* w2   = (const float*)d_in[4];
    const float* w3   = (const float*)d_in[5];
    const float* w4   = (const float*)d_in[6];
    const float* w5   = (const float*)d_in[7];
    const float* s2w0 = (const float*)d_in[8];
    const float* s2w1 = (const float*)d_in[9];
    const float* s2w2 = (const float*)d_in[10];
    const float* fw   = (const float*)d_in[11];

    cmfsm_prep<<<64, 256>>>(w0, w1, w2, w3);

    int sms = 148;
    cudaDeviceGetAttribute(&sms, cudaDevAttrMultiProcessorCount, 0);
    if (sms > NTILES) sms = NTILES;

    cudaFuncSetAttribute(cmfsm_main, cudaFuncAttributeMaxDynamicSharedMemorySize, SMEMSZ);
    cmfsm_main<<<sms, 256, SMEMSZ>>>(lr, hr, w4, w5, s2w0, s2w1, s2w2, fw, (float*)d_out);
}

// round 14
// speedup vs baseline: 1.3182x; 1.2695x over previous
#include <cuda_runtime.h>
#include <cstdint>

typedef unsigned u32;

#define NPX (512 * 1024)
#define LRN (256 * 512)
#define NTILES 4096            // 4096 tiles x 128 px
#define BSTR 132               // act buffer row stride (floats): conflict-free B LDS

// ---------------- packed-bf16 split weights in global scratch ----------------
__device__ __align__(16) u32 g_wh0[128 * 68];
__device__ __align__(16) u32 g_wl0[128 * 68];
__device__ __align__(16) u32 g_wh1[64 * 68];
__device__ __align__(16) u32 g_wl1[64 * 68];
__device__ __align__(16) u32 g_wh2[32 * 36];
__device__ __align__(16) u32 g_wl2[32 * 36];
__device__ __align__(16) u32 g_wh3[16 * 20];
__device__ __align__(16) u32 g_wl3[16 * 20];

__device__ __forceinline__ u32 pkbf(float lo, float hi) {
    u32 r; asm("cvt.rn.bf16x2.f32 %0, %1, %2;" : "=r"(r) : "f"(hi), "f"(lo)); return r;
}
__device__ __forceinline__ float bflo(u32 p) { return __uint_as_float(p << 16); }
__device__ __forceinline__ float bfhi(u32 p) { return __uint_as_float(p & 0xFFFF0000u); }
__device__ __forceinline__ float lrelu(float x) { return fmaxf(x, 0.01f * x); }

// ---------------- prep: fp32 weights -> packed bf16 hi/lo layouts ----------------
__global__ void cmfsm_prep(const float* __restrict__ w0, const float* __restrict__ w1,
                           const float* __restrict__ w2, const float* __restrict__ w3) {
    int t = blockIdx.x * blockDim.x + threadIdx.x;
    int n = gridDim.x * blockDim.x;
    for (int i = t; i < 128 * 64; i += n) {
        int m = i >> 6, kp = i & 63;
        float v0 = w0[m * 128 + 2 * kp], v1 = w0[m * 128 + 2 * kp + 1];
        u32 h = pkbf(v0, v1);
        g_wh0[m * 68 + kp] = h;
        g_wl0[m * 68 + kp] = pkbf(v0 - bflo(h), v1 - bfhi(h));
    }
    for (int i = t; i < 64 * 64; i += n) {
        int m = i >> 6, kp = i & 63;
        float v0 = w1[m * 128 + 2 * kp], v1 = w1[m * 128 + 2 * kp + 1];
        u32 h = pkbf(v0, v1);
        g_wh1[m * 68 + kp] = h;
        g_wl1[m * 68 + kp] = pkbf(v0 - bflo(h), v1 - bfhi(h));
    }
    for (int i = t; i < 32 * 32; i += n) {
        int m = i >> 5, kp = i & 31;
        float v0 = w2[m * 64 + 2 * kp], v1 = w2[m * 64 + 2 * kp + 1];
        u32 h = pkbf(v0, v1);
        g_wh2[m * 36 + kp] = h;
        g_wl2[m * 36 + kp] = pkbf(v0 - bflo(h), v1 - bfhi(h));
    }
    for (int i = t; i < 16 * 16; i += n) {
        int m = i >> 4, kp = i & 15;
        float v0 = w3[m * 32 + 2 * kp], v1 = w3[m * 32 + 2 * kp + 1];
        u32 h = pkbf(v0, v1);
        g_wh3[m * 20 + kp] = h;
        g_wl3[m * 20 + kp] = pkbf(v0 - bflo(h), v1 - bfhi(h));
    }
}

// ---------------- smem layout (bytes) ----------------
#define OBUF  0                         // main act buffer: 128 rows x 132 f32 = 67584
#define OACT2 67584                     // act2 buffer: 64 rows x 132 f32 = 33792
#define OWH0  101376                    // 128x68 u32 = 34816
#define OWL0  136192
#define OWH1  171008                    // 64x68 = 17408
#define OWL1  188416
#define OWH2  205824                    // 32x36 = 4608
#define OWL2  210432
#define OWH3  215040                    // 16x20 = 1280
#define OWL3  216320
#define OSACT 217600                    // 128 px x 17 f32 = 8704
#define OW45  226304                    // w4[128], w5[8], s2w0[9], s2w1[6], s2w2[2], fw[2] = 155 f32
#define SMEMSZ 226944

// ---------------- mma.m16n8k16 bf16 ----------------
__device__ __forceinline__ void mma16(float* c, const u32* a, u32 b0, u32 b1) {
    asm volatile(
        "mma.sync.aligned.m16n8k16.row.col.f32.bf16.bf16.f32 "
        "{%0,%1,%2,%3}, {%4,%5,%6,%7}, {%8,%9}, {%0,%1,%2,%3};"
        : "+f"(c[0]), "+f"(c[1]), "+f"(c[2]), "+f"(c[3])
        : "r"(a[0]), "r"(a[1]), "r"(a[2]), "r"(a[3]), "r"(b0), "r"(b1));
}

// A-fragment in packed-pair space: rows (r, r+8), pair-cols (c, c+4)
__device__ __forceinline__ void lda(const u32* W, int S, int m0, int kp0, int lane, u32* a) {
    int r = lane >> 2, c = lane & 3;
    const u32* p = W + (m0 + r) * S + kp0 + c;
    a[0] = p[0];
    a[2] = p[4];
    a[1] = p[8 * S];
    a[3] = p[8 * S + 4];
}

// GEMM: C[MT][NT][4] += (Wh+Wl) @ (bh+bl), 3-term bf16, consumer-side split. K = 16*KT.
template <int MT, int NT, int KT, int WS>
__device__ __forceinline__ void gemm(const u32* Wh, const u32* Wl, const float* buf,
                                     float* C, int m0, int px0, int lane) {
    const int r = lane >> 2, c = lane & 3;
#pragma unroll 2
    for (int kt = 0; kt < KT; kt++) {
        const int k0 = kt * 16;      // element-k base
        const int kp0 = kt * 8;      // pair base
        u32 ah[MT][4], al[MT][4];
#pragma unroll
        for (int mt = 0; mt < MT; mt++) {
            lda(Wh, WS, m0 + 16 * mt, kp0, lane, ah[mt]);
            lda(Wl, WS, m0 + 16 * mt, kp0, lane, al[mt]);
        }
#pragma unroll
        for (int nt = 0; nt < NT; nt++) {
            const int pxn = px0 + 8 * nt + r;
            float y0 = buf[(k0 + 2 * c) * BSTR + pxn];
            float y1 = buf[(k0 + 2 * c + 1) * BSTR + pxn];
            float y2 = buf[(k0 + 2 * c + 8) * BSTR + pxn];
            float y3 = buf[(k0 + 2 * c + 9) * BSTR + pxn];
            u32 bh0 = pkbf(y0, y1), bh1 = pkbf(y2, y3);
            u32 bl0 = pkbf(y0 - bflo(bh0), y1 - bfhi(bh0));
            u32 bl1 = pkbf(y2 - bflo(bh1), y3 - bfhi(bh1));
#pragma unroll
            for (int mt = 0; mt < MT; mt++) {
                float* cc = C + (mt * NT + nt) * 4;
                mma16(cc, ah[mt], bh0, bh1);
                mma16(cc, ah[mt], bl0, bl1);
                mma16(cc, al[mt], bh0, bh1);
            }
        }
    }
}

// epilogue: lrelu(C) -> dst (fp32 rows, stride BSTR)
template <int MT, int NT>
__device__ __forceinline__ void epi(float* dst, const float* C, int m0, int px0, int lane) {
    const int r = lane >> 2, c = lane & 3;
#pragma unroll
    for (int mt = 0; mt < MT; mt++)
#pragma unroll
        for (int nt = 0; nt < NT; nt++) {
            const float* cc = C + (mt * NT + nt) * 4;
            int ch = m0 + 16 * mt + r;
            int px = px0 + 8 * nt + 2 * c;
            float2 v0 = { lrelu(cc[0]), lrelu(cc[1]) };
            float2 v1 = { lrelu(cc[2]), lrelu(cc[3]) };
            *(float2*)(dst + ch * BSTR + px)       = v0;
            *(float2*)(dst + (ch + 8) * BSTR + px) = v1;
        }
}

// prefetch one tile's lr/hr slices into registers
__device__ __forceinline__ void ldtile(const float* __restrict__ lr,
                                       const float* __restrict__ hr,
                                       int tile, int tid, float* pa, float* pb) {
    const int pxb = tile << 7;
    const int hb  = pxb >> 10;
    const int wbp = pxb & 1023;
    const int g   = tid >> 7;
    const int px  = tid & 127;
    const int li  = ((hb >> 1) << 9) + ((wbp + px) >> 1);
    const float* hp = hr + (size_t)(16 * g) * NPX + (pxb + px);
    const float* lp = lr + (size_t)(16 * g) * LRN + li;
#pragma unroll
    for (int i = 0; i < 16; i++) {
        pa[i] = lp[(size_t)i * LRN];
        pb[i] = hp[(size_t)i * NPX];
    }
}

__global__ void __launch_bounds__(256, 1)
cmfsm_main(const float* __restrict__ lr, const float* __restrict__ hr,
           const float* __restrict__ w4, const float* __restrict__ w5,
           const float* __restrict__ s2w0, const float* __restrict__ s2w1,
           const float* __restrict__ s2w2, const float* __restrict__ fw,
           float* __restrict__ out) {
    extern __shared__ __align__(16) char sm8[];
    float* buf  = (float*)(sm8 + OBUF);
    float* act2 = (float*)(sm8 + OACT2);
    u32* wh0 = (u32*)(sm8 + OWH0);  u32* wl0 = (u32*)(sm8 + OWL0);
    u32* wh1 = (u32*)(sm8 + OWH1);  u32* wl1 = (u32*)(sm8 + OWL1);
    u32* wh2 = (u32*)(sm8 + OWH2);  u32* wl2 = (u32*)(sm8 + OWL2);
    u32* wh3 = (u32*)(sm8 + OWH3);  u32* wl3 = (u32*)(sm8 + OWL3);
    float* sact = (float*)(sm8 + OSACT);
    float* w45  = (float*)(sm8 + OW45);

    const int tid  = threadIdx.x;
    const int wid  = tid >> 5;
    const int lane = tid & 31;

    // one-time copies: weights (L2 scratch) + scalar-stage weights -> smem
    {
        const uint4* s; uint4* d;
        s = (const uint4*)g_wh0; d = (uint4*)wh0;
        for (int i = tid; i < 2176; i += 256) d[i] = s[i];
        s = (const uint4*)g_wl0; d = (uint4*)wl0;
        for (int i = tid; i < 2176; i += 256) d[i] = s[i];
        s = (const uint4*)g_wh1; d = (uint4*)wh1;
        for (int i = tid; i < 1088; i += 256) d[i] = s[i];
        s = (const uint4*)g_wl1; d = (uint4*)wl1;
        for (int i = tid; i < 1088; i += 256) d[i] = s[i];
        s = (const uint4*)g_wh2; d = (uint4*)wh2;
        for (int i = tid; i < 288; i += 256) d[i] = s[i];
        s = (const uint4*)g_wl2; d = (uint4*)wl2;
        for (int i = tid; i < 288; i += 256) d[i] = s[i];
        s = (const uint4*)g_wh3; d = (uint4*)wh3;
        for (int i = tid; i < 80; i += 256) d[i] = s[i];
        s = (const uint4*)g_wl3; d = (uint4*)wl3;
        for (int i = tid; i < 80; i += 256) d[i] = s[i];
        if (tid < 128) w45[tid] = w4[tid];
        if (tid >= 128 && tid < 136) w45[tid] = w5[tid - 128];
        if (tid >= 136 && tid < 145) w45[tid] = s2w0[tid - 136];
        if (tid >= 145 && tid < 151) w45[tid] = s2w1[tid - 145];
        if (tid >= 151 && tid < 153) w45[tid] = s2w2[tid - 151];
        if (tid >= 153 && tid < 155) w45[tid] = fw[tid - 153];
    }

    float pa[16], pb[16];
    ldtile(lr, hr, blockIdx.x, tid, pa, pb);
    __syncthreads();

    for (int tile = blockIdx.x; tile < NTILES; tile += gridDim.x) {
        const int pxb = tile << 7;
        const int hb  = pxb >> 10;
        const int wbp = pxb & 1023;

        // ---- rep build from prefetched regs ----
        {
            const int g  = tid >> 7;
            const int px = tid & 127;
#pragma unroll
            for (int i = 0; i < 16; i++) {
                float a = pa[i], b = pb[i];
                int cch = 16 * g + i;
                buf[cch * BSTR + px]        = a;
                buf[(32 + cch) * BSTR + px] = b;
                buf[(64 + cch) * BSTR + px] = a * b;
                float d = a - b;
                buf[(96 + cch) * BSTR + px] = d * d;
            }
        }
        __syncthreads();

        // issue next tile's prefetch; latency overlaps all 4 GEMMs
        {
            int ntile = tile + gridDim.x;
            if (ntile < NTILES) ldtile(lr, hr, ntile, tid, pa, pb);
        }

        // ---- GEMM1: 128 <- rep(128); warp grid 4(m) x 2(px); in-place epi ----
        {
            float C1[2 * 8 * 4];
#pragma unroll
            for (int i = 0; i < 64; i++) C1[i] = 0.f;
            int m0 = 32 * (wid & 3), px0 = 64 * (wid >> 2);
            gemm<2, 8, 8, 68>(wh0, wl0, buf, C1, m0, px0, lane);
            __syncthreads();
            epi<2, 8>(buf, C1, m0, px0, lane);
        }
        __syncthreads();

        // ---- GEMM2: 64 <- act1(128); epi -> act2 buffer (no pre-sync) ----
        {
            float C2[2 * 4 * 4];
#pragma unroll
            for (int i = 0; i < 32; i++) C2[i] = 0.f;
            int m0 = 32 * (wid & 1), px0 = 32 * (wid >> 1);
            gemm<2, 4, 8, 68>(wh1, wl1, buf, C2, m0, px0, lane);
            epi<2, 4>(act2, C2, m0, px0, lane);
        }
        __syncthreads();

        // ---- GEMM3: 32 <- act2(64); epi -> main buffer rows 0-31 (no pre-sync) ----
        {
            float C3[1 * 4 * 4];
#pragma unroll
            for (int i = 0; i < 16; i++) C3[i] = 0.f;
            int m0 = 16 * (wid & 1), px0 = 32 * (wid >> 1);
            gemm<1, 4, 4, 36>(wh2, wl2, act2, C3, m0, px0, lane);
            epi<1, 4>(buf, C3, m0, px0, lane);
        }
        __syncthreads();

        // ---- GEMM4: 16 <- act3(32); 8 warps x 16 px (NT=2) -> SACT (no pre-sync) ----
        {
            float C4[2 * 4];
#pragma unroll
            for (int i = 0; i < 8; i++) C4[i] = 0.f;
            int px0 = 16 * wid;
            gemm<1, 2, 2, 20>(wh3, wl3, buf, C4, 0, px0, lane);
            const int r = lane >> 2, c = lane & 3;
#pragma unroll
            for (int nt = 0; nt < 2; nt++) {
                const float* cc = C4 + nt * 4;
                int px = px0 + 8 * nt + 2 * c;
                sact[px * 17 + r]           = lrelu(cc[0]);
                sact[(px + 1) * 17 + r]     = lrelu(cc[1]);
                sact[px * 17 + r + 8]       = lrelu(cc[2]);
                sact[(px + 1) * 17 + r + 8] = lrelu(cc[3]);
            }
        }
        __syncthreads();

        // ---- scalar finish: layers 5,6 + weights2 + fuse (exact fp32, smem weights) ----
        if (tid < 128) {
            const float* o4 = sact + tid * 17;
            float w1v = 0.f;
#pragma unroll
            for (int cc = 0; cc < 8; cc++) {
                float n5 = 0.f;
#pragma unroll
                for (int k = 0; k < 16; k++) n5 = fmaf(w45[cc * 16 + k], o4[k], n5);
                w1v = fmaf(w45[128 + cc], n5, w1v);
            }
            const float* sw0f = w45 + 136;
            const float* sw1f = w45 + 145;
            const float* sw2f = w45 + 151;
            const float* fwf  = w45 + 153;
            float dx = ((wbp + tid) & 1) ? 1.0f : -1.0f;
            float dy = (hb & 1) ? 1.0f : -1.0f;
            const float nm = 1.41421356237309515f;
            float t0 = lrelu(sw0f[0] * dx + sw0f[1] * dy + sw0f[2] * nm);
            float t1 = lrelu(sw0f[3] * dx + sw0f[4] * dy + sw0f[5] * nm);
            float t2 = lrelu(sw0f[6] * dx + sw0f[7] * dy + sw0f[8] * nm);
            float u0 = lrelu(sw1f[0] * t0 + sw1f[1] * t1 + sw1f[2] * t2);
            float u1 = lrelu(sw1f[3] * t0 + sw1f[4] * t1 + sw1f[5] * t2);
            float w2v = sw2f[0] * u0 + sw2f[1] * u1;
            out[pxb + tid] = fabsf(fwf[0]) * w1v + fabsf(fwf[1]) * w2v;
        }
        __syncthreads();
    }
}

extern "C" void kernel_launch(void* const* d_in, const int* in_sizes, int n_in,
                              void* d_out, int out_size) {
    const float* lr   = (const float*)d_in[0];
    const float* hr   = (const float*)d_in[1];
    const float* w0   = (const float*)d_in[2];
    const float* w1   = (const float*)d_in[3];
    const float* w2   = (const float*)d_in[4];
    const float* w3   = (const float*)d_in[5];
    const float* w4   = (const float*)d_in[6];
    const float* w5   = (const float*)d_in[7];
    const float* s2w0 = (const float*)d_in[8];
    const float* s2w1 = (const float*)d_in[9];
    const float* s2w2 = (const float*)d_in[10];
    const float* fw   = (const float*)d_in[11];

    cmfsm_prep<<<64, 256>>>(w0, w1, w2, w3);

    int sms = 148;
    cudaDeviceGetAttribute(&sms, cudaDevAttrMultiProcessorCount, 0);
    if (sms > NTILES) sms = NTILES;

    cudaFuncSetAttribute(cmfsm_main, cudaFuncAttributeMaxDynamicSharedMemorySize, SMEMSZ);
    cmfsm_main<<<sms, 256, SMEMSZ>>>(lr, hr, w4, w5, s2w0, s2w1, s2w2, fw, (float*)d_out);
}

// round 15
// speedup vs baseline: 1.4431x; 1.0947x over previous
#include <cuda_runtime.h>
#include <cstdint>

typedef unsigned u32;

#define NPX (512 * 1024)
#define LRN (256 * 512)
#define NTILES 4096            // 4096 tiles x 128 px
#define BSTR 132               // act buffer row stride (floats): conflict-free B LDS

// ---------------- packed-bf16 split weights in global scratch ----------------
__device__ __align__(16) u32 g_wh0[128 * 68];
__device__ __align__(16) u32 g_wl0[128 * 68];
__device__ __align__(16) u32 g_wh1[64 * 68];
__device__ __align__(16) u32 g_wl1[64 * 68];
__device__ __align__(16) u32 g_wh2[32 * 36];
__device__ __align__(16) u32 g_wl2[32 * 36];
__device__ __align__(16) u32 g_wh3[16 * 20];
__device__ __align__(16) u32 g_wl3[16 * 20];
__device__ __align__(16) float g_wc[16];     // wc[k] = sum_c w5[c]*w4[c][k] (layers 5+6 are linear)

__device__ __forceinline__ u32 pkbf(float lo, float hi) {
    u32 r; asm("cvt.rn.bf16x2.f32 %0, %1, %2;" : "=r"(r) : "f"(hi), "f"(lo)); return r;
}
__device__ __forceinline__ float bflo(u32 p) { return __uint_as_float(p << 16); }
__device__ __forceinline__ float bfhi(u32 p) { return __uint_as_float(p & 0xFFFF0000u); }
__device__ __forceinline__ float lrelu(float x) { return fmaxf(x, 0.01f * x); }

// ---------------- prep: fp32 weights -> packed bf16 hi/lo layouts + wc fold ----------------
__global__ void cmfsm_prep(const float* __restrict__ w0, const float* __restrict__ w1,
                           const float* __restrict__ w2, const float* __restrict__ w3,
                           const float* __restrict__ w4, const float* __restrict__ w5) {
    int t = blockIdx.x * blockDim.x + threadIdx.x;
    int n = gridDim.x * blockDim.x;
    for (int i = t; i < 128 * 64; i += n) {
        int m = i >> 6, kp = i & 63;
        float v0 = w0[m * 128 + 2 * kp], v1 = w0[m * 128 + 2 * kp + 1];
        u32 h = pkbf(v0, v1);
        g_wh0[m * 68 + kp] = h;
        g_wl0[m * 68 + kp] = pkbf(v0 - bflo(h), v1 - bfhi(h));
    }
    for (int i = t; i < 64 * 64; i += n) {
        int m = i >> 6, kp = i & 63;
        float v0 = w1[m * 128 + 2 * kp], v1 = w1[m * 128 + 2 * kp + 1];
        u32 h = pkbf(v0, v1);
        g_wh1[m * 68 + kp] = h;
        g_wl1[m * 68 + kp] = pkbf(v0 - bflo(h), v1 - bfhi(h));
    }
    for (int i = t; i < 32 * 32; i += n) {
        int m = i >> 5, kp = i & 31;
        float v0 = w2[m * 64 + 2 * kp], v1 = w2[m * 64 + 2 * kp + 1];
        u32 h = pkbf(v0, v1);
        g_wh2[m * 36 + kp] = h;
        g_wl2[m * 36 + kp] = pkbf(v0 - bflo(h), v1 - bfhi(h));
    }
    for (int i = t; i < 16 * 16; i += n) {
        int m = i >> 4, kp = i & 15;
        float v0 = w3[m * 32 + 2 * kp], v1 = w3[m * 32 + 2 * kp + 1];
        u32 h = pkbf(v0, v1);
        g_wh3[m * 20 + kp] = h;
        g_wl3[m * 20 + kp] = pkbf(v0 - bflo(h), v1 - bfhi(h));
    }
    if (t < 16) {
        float s = 0.f;
        for (int c = 0; c < 8; c++) s = fmaf(w5[c], w4[c * 16 + t], s);
        g_wc[t] = s;
    }
}

// ---------------- smem layout (bytes) ----------------
#define OBUF  0                         // main act buffer: 128 rows x 132 f32 = 67584
#define OACT2 67584                     // act2 buffer: 64 rows x 132 f32 = 33792
#define OWH0  101376                    // 128x68 u32 = 34816
#define OWL0  136192
#define OWH1  171008                    // 64x68 = 17408
#define OWL1  188416
#define OWH2  205824                    // 32x36 = 4608
#define OWL2  210432
#define OWH3  215040                    // 16x20 = 1280
#define OWL3  216320
#define OSACT 217600                    // 128 px x 17 f32 = 8704
#define OW45  226304                    // wc[16], s2w0[9], s2w1[6], s2w2[2], fw[2] = 35 f32
#define SMEMSZ 226944

// ---------------- mma.m16n8k16 bf16 ----------------
__device__ __forceinline__ void mma16(float* c, const u32* a, u32 b0, u32 b1) {
    asm volatile(
        "mma.sync.aligned.m16n8k16.row.col.f32.bf16.bf16.f32 "
        "{%0,%1,%2,%3}, {%4,%5,%6,%7}, {%8,%9}, {%0,%1,%2,%3};"
        : "+f"(c[0]), "+f"(c[1]), "+f"(c[2]), "+f"(c[3])
        : "r"(a[0]), "r"(a[1]), "r"(a[2]), "r"(a[3]), "r"(b0), "r"(b1));
}

// A-fragment in packed-pair space: rows (r, r+8), pair-cols (c, c+4)
__device__ __forceinline__ void lda(const u32* W, int S, int m0, int kp0, int lane, u32* a) {
    int r = lane >> 2, c = lane & 3;
    const u32* p = W + (m0 + r) * S + kp0 + c;
    a[0] = p[0];
    a[2] = p[4];
    a[1] = p[8 * S];
    a[3] = p[8 * S + 4];
}

// GEMM: C[MT][NT][4] += (Wh+Wl) @ (bh+bl), 3-term bf16, consumer-side split. K = 16*KT.
template <int MT, int NT, int KT, int WS>
__device__ __forceinline__ void gemm(const u32* Wh, const u32* Wl, const float* buf,
                                     float* C, int m0, int px0, int lane) {
    const int r = lane >> 2, c = lane & 3;
#pragma unroll 2
    for (int kt = 0; kt < KT; kt++) {
        const int k0 = kt * 16;      // element-k base
        const int kp0 = kt * 8;      // pair base
        u32 ah[MT][4], al[MT][4];
#pragma unroll
        for (int mt = 0; mt < MT; mt++) {
            lda(Wh, WS, m0 + 16 * mt, kp0, lane, ah[mt]);
            lda(Wl, WS, m0 + 16 * mt, kp0, lane, al[mt]);
        }
#pragma unroll
        for (int nt = 0; nt < NT; nt++) {
            const int pxn = px0 + 8 * nt + r;
            float y0 = buf[(k0 + 2 * c) * BSTR + pxn];
            float y1 = buf[(k0 + 2 * c + 1) * BSTR + pxn];
            float y2 = buf[(k0 + 2 * c + 8) * BSTR + pxn];
            float y3 = buf[(k0 + 2 * c + 9) * BSTR + pxn];
            u32 bh0 = pkbf(y0, y1), bh1 = pkbf(y2, y3);
            u32 bl0 = pkbf(y0 - bflo(bh0), y1 - bfhi(bh0));
            u32 bl1 = pkbf(y2 - bflo(bh1), y3 - bfhi(bh1));
#pragma unroll
            for (int mt = 0; mt < MT; mt++) {
                float* cc = C + (mt * NT + nt) * 4;
                mma16(cc, ah[mt], bh0, bh1);
                mma16(cc, ah[mt], bl0, bl1);
                mma16(cc, al[mt], bh0, bh1);
            }
        }
    }
}

// epilogue: lrelu(C) -> dst (fp32 rows, stride BSTR)
template <int MT, int NT>
__device__ __forceinline__ void epi(float* dst, const float* C, int m0, int px0, int lane) {
    const int r = lane >> 2, c = lane & 3;
#pragma unroll
    for (int mt = 0; mt < MT; mt++)
#pragma unroll
        for (int nt = 0; nt < NT; nt++) {
            const float* cc = C + (mt * NT + nt) * 4;
            int ch = m0 + 16 * mt + r;
            int px = px0 + 8 * nt + 2 * c;
            float2 v0 = { lrelu(cc[0]), lrelu(cc[1]) };
            float2 v1 = { lrelu(cc[2]), lrelu(cc[3]) };
            *(float2*)(dst + ch * BSTR + px)       = v0;
            *(float2*)(dst + (ch + 8) * BSTR + px) = v1;
        }
}

// prefetch one tile's lr/hr slices into registers
__device__ __forceinline__ void ldtile(const float* __restrict__ lr,
                                       const float* __restrict__ hr,
                                       int tile, int tid, float* pa, float* pb) {
    const int pxb = tile << 7;
    const int hb  = pxb >> 10;
    const int wbp = pxb & 1023;
    const int g   = tid >> 7;
    const int px  = tid & 127;
    const int li  = ((hb >> 1) << 9) + ((wbp + px) >> 1);
    const float* hp = hr + (size_t)(16 * g) * NPX + (pxb + px);
    const float* lp = lr + (size_t)(16 * g) * LRN + li;
#pragma unroll
    for (int i = 0; i < 16; i++) {
        pa[i] = lp[(size_t)i * LRN];
        pb[i] = hp[(size_t)i * NPX];
    }
}

__global__ void __launch_bounds__(256, 1)
cmfsm_main(const float* __restrict__ lr, const float* __restrict__ hr,
           const float* __restrict__ s2w0, const float* __restrict__ s2w1,
           const float* __restrict__ s2w2, const float* __restrict__ fw,
           float* __restrict__ out) {
    extern __shared__ __align__(16) char sm8[];
    float* buf  = (float*)(sm8 + OBUF);
    float* act2 = (float*)(sm8 + OACT2);
    u32* wh0 = (u32*)(sm8 + OWH0);  u32* wl0 = (u32*)(sm8 + OWL0);
    u32* wh1 = (u32*)(sm8 + OWH1);  u32* wl1 = (u32*)(sm8 + OWL1);
    u32* wh2 = (u32*)(sm8 + OWH2);  u32* wl2 = (u32*)(sm8 + OWL2);
    u32* wh3 = (u32*)(sm8 + OWH3);  u32* wl3 = (u32*)(sm8 + OWL3);
    float* sact = (float*)(sm8 + OSACT);
    float* w45  = (float*)(sm8 + OW45);

    const int tid  = threadIdx.x;
    const int wid  = tid >> 5;
    const int lane = tid & 31;

    // one-time copies: weights (L2 scratch) + scalar-stage weights -> smem
    {
        const uint4* s; uint4* d;
        s = (const uint4*)g_wh0; d = (uint4*)wh0;
        for (int i = tid; i < 2176; i += 256) d[i] = s[i];
        s = (const uint4*)g_wl0; d = (uint4*)wl0;
        for (int i = tid; i < 2176; i += 256) d[i] = s[i];
        s = (const uint4*)g_wh1; d = (uint4*)wh1;
        for (int i = tid; i < 1088; i += 256) d[i] = s[i];
        s = (const uint4*)g_wl1; d = (uint4*)wl1;
        for (int i = tid; i < 1088; i += 256) d[i] = s[i];
        s = (const uint4*)g_wh2; d = (uint4*)wh2;
        for (int i = tid; i < 288; i += 256) d[i] = s[i];
        s = (const uint4*)g_wl2; d = (uint4*)wl2;
        for (int i = tid; i < 288; i += 256) d[i] = s[i];
        s = (const uint4*)g_wh3; d = (uint4*)wh3;
        for (int i = tid; i < 80; i += 256) d[i] = s[i];
        s = (const uint4*)g_wl3; d = (uint4*)wl3;
        for (int i = tid; i < 80; i += 256) d[i] = s[i];
        if (tid < 16) w45[tid] = g_wc[tid];
        if (tid >= 16 && tid < 25) w45[tid] = s2w0[tid - 16];
        if (tid >= 25 && tid < 31) w45[tid] = s2w1[tid - 25];
        if (tid >= 31 && tid < 33) w45[tid] = s2w2[tid - 31];
        if (tid >= 33 && tid < 35) w45[tid] = fw[tid - 33];
    }

    float pa[16], pb[16];
    ldtile(lr, hr, blockIdx.x, tid, pa, pb);
    __syncthreads();

    for (int tile = blockIdx.x; tile < NTILES; tile += gridDim.x) {
        const int pxb = tile << 7;
        const int hb  = pxb >> 10;
        const int wbp = pxb & 1023;

        // ---- rep build from prefetched regs ----
        {
            const int g  = tid >> 7;
            const int px = tid & 127;
#pragma unroll
            for (int i = 0; i < 16; i++) {
                float a = pa[i], b = pb[i];
                int cch = 16 * g + i;
                buf[cch * BSTR + px]        = a;
                buf[(32 + cch) * BSTR + px] = b;
                buf[(64 + cch) * BSTR + px] = a * b;
                float d = a - b;
                buf[(96 + cch) * BSTR + px] = d * d;
            }
        }
        __syncthreads();

        // issue next tile's prefetch; latency overlaps all 4 GEMMs
        {
            int ntile = tile + gridDim.x;
            if (ntile < NTILES) ldtile(lr, hr, ntile, tid, pa, pb);
        }

        // ---- GEMM1: 128 <- rep(128); warp grid 2(m) x 4(px), MT=4 NT=4 ----
        {
            float C1[4 * 4 * 4];
#pragma unroll
            for (int i = 0; i < 64; i++) C1[i] = 0.f;
            int m0 = 64 * (wid & 1), px0 = 32 * (wid >> 1);
            gemm<4, 4, 8, 68>(wh0, wl0, buf, C1, m0, px0, lane);
            __syncthreads();
            epi<4, 4>(buf, C1, m0, px0, lane);
        }
        __syncthreads();

        // ---- GEMM2: 64 <- act1(128); warp grid 1(m) x 8(px), MT=4 NT=2 -> act2 ----
        {
            float C2[4 * 2 * 4];
#pragma unroll
            for (int i = 0; i < 32; i++) C2[i] = 0.f;
            int px0 = 16 * wid;
            gemm<4, 2, 8, 68>(wh1, wl1, buf, C2, 0, px0, lane);
            epi<4, 2>(act2, C2, 0, px0, lane);
        }
        __syncthreads();

        // ---- GEMM3: 32 <- act2(64); warp grid 1(m) x 8(px), MT=2 NT=2 -> buf ----
        {
            float C3[2 * 2 * 4];
#pragma unroll
            for (int i = 0; i < 16; i++) C3[i] = 0.f;
            int px0 = 16 * wid;
            gemm<2, 2, 4, 36>(wh2, wl2, act2, C3, 0, px0, lane);
            epi<2, 2>(buf, C3, 0, px0, lane);
        }
        __syncthreads();

        // ---- GEMM4: 16 <- act3(32); 8 warps x 16 px (NT=2) -> SACT ----
        {
            float C4[2 * 4];
#pragma unroll
            for (int i = 0; i < 8; i++) C4[i] = 0.f;
            int px0 = 16 * wid;
            gemm<1, 2, 2, 20>(wh3, wl3, buf, C4, 0, px0, lane);
            const int r = lane >> 2, c = lane & 3;
#pragma unroll
            for (int nt = 0; nt < 2; nt++) {
                const float* cc = C4 + nt * 4;
                int px = px0 + 8 * nt + 2 * c;
                sact[px * 17 + r]           = lrelu(cc[0]);
                sact[(px + 1) * 17 + r]     = lrelu(cc[1]);
                sact[px * 17 + r + 8]       = lrelu(cc[2]);
                sact[(px + 1) * 17 + r + 8] = lrelu(cc[3]);
            }
        }
        __syncthreads();

        // ---- scalar finish: folded layers 5+6 (wc.o4) + weights2 + fuse ----
        if (tid < 128) {
            const float* o4 = sact + tid * 17;
            float w1v = 0.f;
#pragma unroll
            for (int k = 0; k < 16; k++) w1v = fmaf(w45[k], o4[k], w1v);
            const float* sw0f = w45 + 16;
            const float* sw1f = w45 + 25;
            const float* sw2f = w45 + 31;
            const float* fwf  = w45 + 33;
            float dx = ((wbp + tid) & 1) ? 1.0f : -1.0f;
            float dy = (hb & 1) ? 1.0f : -1.0f;
            const float nm = 1.41421356237309515f;
            float t0 = lrelu(sw0f[0] * dx + sw0f[1] * dy + sw0f[2] * nm);
            float t1 = lrelu(sw0f[3] * dx + sw0f[4] * dy + sw0f[5] * nm);
            float t2 = lrelu(sw0f[6] * dx + sw0f[7] * dy + sw0f[8] * nm);
            float u0 = lrelu(sw1f[0] * t0 + sw1f[1] * t1 + sw1f[2] * t2);
            float u1 = lrelu(sw1f[3] * t0 + sw1f[4] * t1 + sw1f[5] * t2);
            float w2v = sw2f[0] * u0 + sw2f[1] * u1;
            out[pxb + tid] = fabsf(fwf[0]) * w1v + fabsf(fwf[1]) * w2v;
        }
        __syncthreads();
    }
}

extern "C" void kernel_launch(void* const* d_in, const int* in_sizes, int n_in,
                              void* d_out, int out_size) {
    const float* lr   = (const float*)d_in[0];
    const float* hr   = (const float*)d_in[1];
    const float* w0   = (const float*)d_in[2];
    const float* w1   = (const float*)d_in[3];
    const float* w2   = (const float*)d_in[4];
    const float* w3   = (const float*)d_in[5];
    const float* w4   = (const float*)d_in[6];
    const float* w5   = (const float*)d_in[7];
    const float* s2w0 = (const float*)d_in[8];
    const float* s2w1 = (const float*)d_in[9];
    const float* s2w2 = (const float*)d_in[10];
    const float* fw   = (const float*)d_in[11];

    cmfsm_prep<<<64, 256>>>(w0, w1, w2, w3, w4, w5);

    int sms = 148;
    cudaDeviceGetAttribute(&sms, cudaDevAttrMultiProcessorCount, 0);
    if (sms > NTILES) sms = NTILES;

    cudaFuncSetAttribute(cmfsm_main, cudaFuncAttributeMaxDynamicSharedMemorySize, SMEMSZ);
    cmfsm_main<<<sms, 256, SMEMSZ>>>(lr, hr, s2w0, s2w1, s2w2, fw, (float*)d_out);
}